// round 15
// baseline (speedup 1.0000x reference)
#include <cuda_runtime.h>
#include <cstdint>

// SpikeFP32ScaleBy2K — streaming bit-circuit kernel (FINAL, roofline-frozen).
//   out = (k == ±0) ? x : x with exponent field := (e_x + kf) & 0xFF
//   kf = s_k ? -|k| : |k|,  |k| = (0x80 | top7(m_k)) >> (7 - ((e_k-127)&7))
// Bits stored big-endian as 0.0/1.0 floats, 32 per row.
//
// Layout: 8 lanes per row, one float4 (4 bits) per lane -> fully coalesced
// 16B accesses; row words assembled via 3-level shfl_xor OR-butterfly.
//
// Complete axis sweep (R1-R14):
//   layout (this form)            109.0-109.9us kernel, n=3  <- BEST
//   block=512                     111.0us (-1.5%, occ 80.6->76.7%)
//   persistent grid-stride        117.3us (-7%)
//   far-stride MLP=4              111.8us (-2%)
//   adjacent MLP=4, 256-bit ops,
//   cache hints, tail removal,
//   packing-cost reduction        all neutral
// 6.94-6.96 TB/s = 87% of HBM spec; DRAM 85% with issue 33%/ALU 38%/L1 36%
// all slack; traffic (768 MB) irreducible. DRAM-scheduler-bound ceiling.

__global__ __launch_bounds__(256) void spike_scale_kernel(
    const uint4* __restrict__ x,
    const uint4* __restrict__ k,
    uint4* __restrict__ out)
{
    int t = blockIdx.x * blockDim.x + threadIdx.x;

    const unsigned sh = 28u - 4u * ((unsigned)t & 7u);   // nibble pos (BE order)

    uint4 xu = x[t];
    uint4 ku = k[t];

    // Pack via bit 23: 1.0f (0x3F800000) has it set, 0.0f doesn't.
    unsigned xw = ( ((xu.x >> 20) & 8u) | ((xu.y >> 21) & 4u) |
                    ((xu.z >> 22) & 2u) | ((xu.w >> 23) & 1u) ) << sh;
    unsigned kw = ( ((ku.x >> 20) & 8u) | ((ku.y >> 21) & 4u) |
                    ((ku.z >> 22) & 2u) | ((ku.w >> 23) & 1u) ) << sh;

    // OR-butterfly across the 8 contiguous lanes of this row.
    #pragma unroll
    for (int m = 1; m <= 4; m <<= 1) {
        xw |= __shfl_xor_sync(0xFFFFFFFFu, xw, m);
        kw |= __shfl_xor_sync(0xFFFFFFFFu, kw, m);
    }
    // xw/kw now hold full words: sign@31, exp@30..23, mant@22..0.

    unsigned e_k   = (kw >> 23) & 0xFFu;
    unsigned s_k   = kw >> 31;
    unsigned kzero = ((kw & 0x7FFFFFFFu) == 0u);

    unsigned sh3  = (e_k - 127u) & 7u;
    unsigned val  = 0x80u | ((kw >> 16) & 0x7Fu);
    unsigned kabs = val >> (7u - sh3);
    unsigned kf   = s_k ? ((0u - kabs) & 0xFFu) : kabs;

    unsigned e_new = (((xw >> 23) & 0xFFu) + kf) & 0xFFu;
    unsigned ow    = kzero ? xw : ((xw & 0x807FFFFFu) | (e_new << 23));

    // Unpack this lane's 4 output bits; store non-temporal (never re-read).
    unsigned b = ow >> sh;
    uint4 o;
    o.x = (b & 8u) ? 0x3F800000u : 0u;
    o.y = (b & 4u) ? 0x3F800000u : 0u;
    o.z = (b & 2u) ? 0x3F800000u : 0u;
    o.w = (b & 1u) ? 0x3F800000u : 0u;
    __stcs(&out[t], o);
}

extern "C" void kernel_launch(void* const* d_in, const int* in_sizes, int n_in,
                              void* d_out, int out_size)
{
    const uint4* x = (const uint4*)d_in[0];
    const uint4* k = (const uint4*)d_in[1];
    uint4* o = (uint4*)d_out;

    int n4 = in_sizes[0] / 4;          // 2^24 float4s — divisible by 256
    int threads = 256;
    int blocks  = n4 / threads;        // exact; no tail
    spike_scale_kernel<<<blocks, threads>>>(x, k, o);
}

// round 17
// speedup vs baseline: 1.0005x; 1.0005x over previous
#include <cuda_runtime.h>
#include <cstdint>

// SpikeFP32ScaleBy2K — streaming bit-circuit kernel (roofline form, block=128).
//   out = (k == ±0) ? x : x with exponent field := (e_x + kf) & 0xFF
//   kf = s_k ? -|k| : |k|,  |k| = (0x80 | top7(m_k)) >> (7 - ((e_k-127)&7))
// Bits stored big-endian as 0.0/1.0 floats, 32 per row.
//
// Layout: 8 lanes per row, one float4 (4 bits) per lane -> fully coalesced
// 16B accesses; row words assembled via 3-level shfl_xor OR-butterfly.
// Identical body to the frozen form (109.0-109.7us kernel, n=4, 87% of HBM
// spec); only delta is blockDim 256 -> 128. Rationale: block=512 cost 1.5%
// via occupancy (80.6->76.7%, coarse wave-drain granularity); 128 tests the
// opposite direction (16 CTAs/SM, finer drain quanta, occ up). Brackets the
// block-size curve: 128/256/512.
// (Resubmission — R16 failed on container acquisition, kernel unmeasured.)

__global__ __launch_bounds__(128) void spike_scale_kernel(
    const uint4* __restrict__ x,
    const uint4* __restrict__ k,
    uint4* __restrict__ out)
{
    int t = blockIdx.x * blockDim.x + threadIdx.x;

    const unsigned sh = 28u - 4u * ((unsigned)t & 7u);   // nibble pos (BE order)

    uint4 xu = x[t];
    uint4 ku = k[t];

    // Pack via bit 23: 1.0f (0x3F800000) has it set, 0.0f doesn't.
    unsigned xw = ( ((xu.x >> 20) & 8u) | ((xu.y >> 21) & 4u) |
                    ((xu.z >> 22) & 2u) | ((xu.w >> 23) & 1u) ) << sh;
    unsigned kw = ( ((ku.x >> 20) & 8u) | ((ku.y >> 21) & 4u) |
                    ((ku.z >> 22) & 2u) | ((ku.w >> 23) & 1u) ) << sh;

    // OR-butterfly across the 8 contiguous lanes of this row.
    #pragma unroll
    for (int m = 1; m <= 4; m <<= 1) {
        xw |= __shfl_xor_sync(0xFFFFFFFFu, xw, m);
        kw |= __shfl_xor_sync(0xFFFFFFFFu, kw, m);
    }
    // xw/kw now hold full words: sign@31, exp@30..23, mant@22..0.

    unsigned e_k   = (kw >> 23) & 0xFFu;
    unsigned s_k   = kw >> 31;
    unsigned kzero = ((kw & 0x7FFFFFFFu) == 0u);

    unsigned sh3  = (e_k - 127u) & 7u;
    unsigned val  = 0x80u | ((kw >> 16) & 0x7Fu);
    unsigned kabs = val >> (7u - sh3);
    unsigned kf   = s_k ? ((0u - kabs) & 0xFFu) : kabs;

    unsigned e_new = (((xw >> 23) & 0xFFu) + kf) & 0xFFu;
    unsigned ow    = kzero ? xw : ((xw & 0x807FFFFFu) | (e_new << 23));

    // Unpack this lane's 4 output bits; store non-temporal (never re-read).
    unsigned b = ow >> sh;
    uint4 o;
    o.x = (b & 8u) ? 0x3F800000u : 0u;
    o.y = (b & 4u) ? 0x3F800000u : 0u;
    o.z = (b & 2u) ? 0x3F800000u : 0u;
    o.w = (b & 1u) ? 0x3F800000u : 0u;
    __stcs(&out[t], o);
}

extern "C" void kernel_launch(void* const* d_in, const int* in_sizes, int n_in,
                              void* d_out, int out_size)
{
    const uint4* x = (const uint4*)d_in[0];
    const uint4* k = (const uint4*)d_in[1];
    uint4* o = (uint4*)d_out;

    int n4 = in_sizes[0] / 4;          // 2^24 float4s — divisible by 128
    int threads = 128;
    int blocks  = n4 / threads;        // exact; no tail
    spike_scale_kernel<<<blocks, threads>>>(x, k, o);
}